// round 8
// baseline (speedup 1.0000x reference)
#include <cuda_runtime.h>

// SymmetryControl (square-symmetry branch), B=16,C=96,H=96,W=96.
// Barrier-free pair-orbit kernel + 2-item L2-prefetch software pipeline:
//   - each thread handles work items u and u+T (T = total threads)
//   - before loading item0, it prefetches item1's 6 cache lines into L2
//     (register-free), so DRAM keeps streaming during item0's compute burst
//   - item1's LDGs then hit L2 (~240cyc vs ~600)
// Thread work item (row, tx in 0..2): owns orbits A={tx+6k}, B={(5-tx)+6k}
// (k=0..3, f4 units) of its 24-f4 row; loads 16 f4, computes 8 output f4.
// Output elem i = 4t+c:
//   shifts: f4 (t+18)%24, (t+12)%24, (t+6)%24, component c
//   flips:  f4 (5-t)%24 (slot (4-m)&3 of partner orbit) and (11-t)%24
//           (slot (1-m)&3), component 3-c (reversed)

#define W4 24
#define NT 128
#define ITEMS 2

__device__ __forceinline__ void prefetch_l2(const void* p) {
    asm volatile("prefetch.global.L2 [%0];" :: "l"(p));
}

__device__ __forceinline__ float4 orbit_out(
    const float4 p0, const float4 pa, const float4 pb, const float4 pc,
    const float4 w0, const float4 wa, const float4 wb, const float4 wc,
    const float4 qf, const float4 vf, const float4 qg, const float4 vg,
    float g0, float g1, float g2, float g3, float g4)
{
    float4 o;
    {   float a = p0.x;
        a = fmaf(g0, pa.x, a); a = fmaf(g1, pb.x, a); a = fmaf(g2, pc.x, a);
        a = fmaf(g3, qf.w, a); a = fmaf(g4, qg.w, a);
        float d = w0.x;
        d = fmaf(g0, wa.x, d); d = fmaf(g1, wb.x, d); d = fmaf(g2, wc.x, d);
        d = fmaf(g3, vf.w, d); d = fmaf(g4, vg.w, d);
        o.x = __fdividef(a, d); }
    {   float a = p0.y;
        a = fmaf(g0, pa.y, a); a = fmaf(g1, pb.y, a); a = fmaf(g2, pc.y, a);
        a = fmaf(g3, qf.z, a); a = fmaf(g4, qg.z, a);
        float d = w0.y;
        d = fmaf(g0, wa.y, d); d = fmaf(g1, wb.y, d); d = fmaf(g2, wc.y, d);
        d = fmaf(g3, vf.z, d); d = fmaf(g4, vg.z, d);
        o.y = __fdividef(a, d); }
    {   float a = p0.z;
        a = fmaf(g0, pa.z, a); a = fmaf(g1, pb.z, a); a = fmaf(g2, pc.z, a);
        a = fmaf(g3, qf.y, a); a = fmaf(g4, qg.y, a);
        float d = w0.z;
        d = fmaf(g0, wa.z, d); d = fmaf(g1, wb.z, d); d = fmaf(g2, wc.z, d);
        d = fmaf(g3, vf.y, d); d = fmaf(g4, vg.y, d);
        o.z = __fdividef(a, d); }
    {   float a = p0.w;
        a = fmaf(g0, pa.w, a); a = fmaf(g1, pb.w, a); a = fmaf(g2, pc.w, a);
        a = fmaf(g3, qf.x, a); a = fmaf(g4, qg.x, a);
        float d = w0.w;
        d = fmaf(g0, wa.w, d); d = fmaf(g1, wb.w, d); d = fmaf(g2, wc.w, d);
        d = fmaf(g3, vf.x, d); d = fmaf(g4, vg.x, d);
        o.w = __fdividef(a, d); }
    return o;
}

__device__ __forceinline__ void do_item(
    int unit,
    const float4* __restrict__ x4, const float* __restrict__ s,
    const float4* __restrict__ w4, float4* __restrict__ out4,
    int rows_per_batch)
{
    const int tx  = unit % 3;
    const int row = unit / 3;
    const int sx  = 5 - tx;
    const size_t base = (size_t)row * W4;

    const int b = row / rows_per_batch;
    const float g0 = 1.0f / (1.0f + __expf(-s[b * 5 + 0]));
    const float g1 = 1.0f / (1.0f + __expf(-s[b * 5 + 1]));
    const float g2 = 1.0f / (1.0f + __expf(-s[b * 5 + 2]));
    const float g3 = 1.0f / (1.0f + __expf(-s[b * 5 + 3]));
    const float g4 = 1.0f / (1.0f + __expf(-s[b * 5 + 4]));

    float4 PA[4], WA[4], PB[4], WB[4];
#pragma unroll
    for (int k = 0; k < 4; k++) {
        const float4 xa = __ldcs(&x4[base + tx + 6 * k]);
        const float4 xb = __ldcs(&x4[base + sx + 6 * k]);
        WA[k] = __ldcs(&w4[base + tx + 6 * k]);
        WB[k] = __ldcs(&w4[base + sx + 6 * k]);
        PA[k] = make_float4(xa.x * WA[k].x, xa.y * WA[k].y,
                            xa.z * WA[k].z, xa.w * WA[k].w);
        PB[k] = make_float4(xb.x * WB[k].x, xb.y * WB[k].y,
                            xb.z * WB[k].z, xb.w * WB[k].w);
    }

#pragma unroll
    for (int m = 0; m < 4; m++) {
        const int m1 = (m + 1) & 3;
        const int m2 = (m + 2) & 3;
        const int m3 = (m + 3) & 3;
        const int kf90  = (4 - m) & 3;
        const int kf180 = (1 - m) & 3;

        const float4 oA = orbit_out(PA[m], PA[m3], PA[m2], PA[m1],
                                    WA[m], WA[m3], WA[m2], WA[m1],
                                    PB[kf90], WB[kf90], PB[kf180], WB[kf180],
                                    g0, g1, g2, g3, g4);
        const float4 oB = orbit_out(PB[m], PB[m3], PB[m2], PB[m1],
                                    WB[m], WB[m3], WB[m2], WB[m1],
                                    PA[kf90], WA[kf90], PA[kf180], WA[kf180],
                                    g0, g1, g2, g3, g4);

        __stcs(&out4[base + tx + 6 * m], oA);
        __stcs(&out4[base + sx + 6 * m], oB);
    }
}

__global__ __launch_bounds__(NT, 5)
void symmetry_control_pf(const float4* __restrict__ x4,
                         const float*  __restrict__ s,
                         const float4* __restrict__ w4,
                         float4* __restrict__ out4,
                         int rows_per_batch /* 9216 */,
                         int stride_units   /* total threads */)
{
    const int u0 = blockIdx.x * NT + threadIdx.x;
    const int u1 = u0 + stride_units;

    // Prefetch item1's two rows (x and w, 3 lines each) into L2 while item0
    // is loaded and computed. Register-free; duplicates across the 3 threads
    // of a row dedup at L2.
    {
        const size_t r1 = (size_t)(u1 / 3) * (W4 * 16);   // byte offset of row
        const char* px = (const char*)x4 + r1;
        const char* pw = (const char*)w4 + r1;
        prefetch_l2(px);       prefetch_l2(px + 128);  prefetch_l2(px + 256);
        prefetch_l2(pw);       prefetch_l2(pw + 128);  prefetch_l2(pw + 256);
    }

    do_item(u0, x4, s, w4, out4, rows_per_batch);
    do_item(u1, x4, s, w4, out4, rows_per_batch);
}

extern "C" void kernel_launch(void* const* d_in, const int* in_sizes, int n_in,
                              void* d_out, int out_size)
{
    const float4* x4 = (const float4*)d_in[0];
    const float*  s  = (const float*)d_in[1];
    const float4* w4 = (const float4*)d_in[2];
    float4* out4 = (float4*)d_out;

    const long long total = in_sizes[0];          // B*C*H*W = 14,155,776
    const int B = in_sizes[1] / 5;                // 16
    const long long rows = total / 96;            // 147,456
    const int rows_per_batch = (int)(rows / B);   // 9216

    const long long units   = rows * 3;           // 442,368
    const int stride_units  = (int)(units / ITEMS);  // 221,184
    const long long nblocks = stride_units / NT;     // 1728 (exact)
    symmetry_control_pf<<<(unsigned)nblocks, NT>>>(x4, s, w4, out4,
                                                   rows_per_batch, stride_units);
}

// round 9
// speedup vs baseline: 1.1882x; 1.1882x over previous
#include <cuda_runtime.h>

// SymmetryControl (square-symmetry branch), B=16,C=96,H=96,W=96.
// Butterfly-orbit kernel: orbit pair (p, 5-p) of a row maps to adjacent lanes
// (even/odd), so each thread holds ONE orbit (4 f4 of p=x*w + 4 f4 of w) and
// gets the partner orbit's values via shfl.bfly(xor=1). Halves register
// pressure vs the pair-fused kernel -> ~2x resident warps.
//
// Output elem i = 4t+c:
//   shifts: f4 (t+18)%24, (t+12)%24, (t+6)%24, component c
//   flips:  f4 (5-t)%24 (partner slot (4-m)&3) and (11-t)%24 (slot (1-m)&3),
//           component 3-c (reversed)

#define W4 24
#define NT 128

__device__ __forceinline__ float4 shfl_bfly4(float4 v) {
    float4 r;
    r.x = __shfl_xor_sync(0xffffffffu, v.x, 1);
    r.y = __shfl_xor_sync(0xffffffffu, v.y, 1);
    r.z = __shfl_xor_sync(0xffffffffu, v.z, 1);
    r.w = __shfl_xor_sync(0xffffffffu, v.w, 1);
    return r;
}

__global__ __launch_bounds__(NT, 7)
void symmetry_control_bfly(const float4* __restrict__ x4,
                           const float*  __restrict__ s,
                           const float4* __restrict__ w4,
                           float4* __restrict__ out4,
                           int rows_per_batch /* C*H = 9216 */)
{
    // pair id and side: lanes (2q, 2q+1) hold orbits (p, 5-p) of one row.
    const int tid   = blockIdx.x * NT + threadIdx.x;
    const int gpair = tid >> 1;
    const int side  = tid & 1;
    const int row   = gpair / 3;
    const int p     = gpair % 3;
    const int o     = side ? (5 - p) : p;      // my orbit id (0..5)
    const size_t base = (size_t)row * W4;

    // Gates (latency hidden under bulk loads below).
    const int b = row / rows_per_batch;
    const float g0 = 1.0f / (1.0f + __expf(-s[b * 5 + 0]));
    const float g1 = 1.0f / (1.0f + __expf(-s[b * 5 + 1]));
    const float g2 = 1.0f / (1.0f + __expf(-s[b * 5 + 2]));
    const float g3 = 1.0f / (1.0f + __expf(-s[b * 5 + 3]));
    const float g4 = 1.0f / (1.0f + __expf(-s[b * 5 + 4]));

    // My orbit: 8 independent streaming LDG.128.
    float4 P[4], W[4];
#pragma unroll
    for (int k = 0; k < 4; k++) {
        const float4 xv = __ldcs(&x4[base + o + 6 * k]);
        W[k] = __ldcs(&w4[base + o + 6 * k]);
        P[k] = make_float4(xv.x * W[k].x, xv.y * W[k].y,
                           xv.z * W[k].z, xv.w * W[k].w);
    }

#pragma unroll
    for (int m = 0; m < 4; m++) {
        const int m1 = (m + 1) & 3;      // +6  f4 (270deg)
        const int m2 = (m + 2) & 3;      // +12 f4 (180deg)
        const int m3 = (m + 3) & 3;      // +18 f4 (90deg)
        const int kf90  = (4 - m) & 3;   // flip90  slot in partner orbit
        const int kf180 = (1 - m) & 3;   // flip180 slot in partner orbit

        // Partner orbit's values for this m (components reversed in use).
        const float4 qf = shfl_bfly4(P[kf90]);
        const float4 vf = shfl_bfly4(W[kf90]);
        const float4 qg = shfl_bfly4(P[kf180]);
        const float4 vg = shfl_bfly4(W[kf180]);

        const float4 p0 = P[m], pa = P[m3], pb = P[m2], pc = P[m1];
        const float4 w0 = W[m], wa = W[m3], wb = W[m2], wc = W[m1];

        float4 oo;
        {   float a = p0.x;
            a = fmaf(g0, pa.x, a); a = fmaf(g1, pb.x, a); a = fmaf(g2, pc.x, a);
            a = fmaf(g3, qf.w, a); a = fmaf(g4, qg.w, a);
            float d = w0.x;
            d = fmaf(g0, wa.x, d); d = fmaf(g1, wb.x, d); d = fmaf(g2, wc.x, d);
            d = fmaf(g3, vf.w, d); d = fmaf(g4, vg.w, d);
            oo.x = __fdividef(a, d); }
        {   float a = p0.y;
            a = fmaf(g0, pa.y, a); a = fmaf(g1, pb.y, a); a = fmaf(g2, pc.y, a);
            a = fmaf(g3, qf.z, a); a = fmaf(g4, qg.z, a);
            float d = w0.y;
            d = fmaf(g0, wa.y, d); d = fmaf(g1, wb.y, d); d = fmaf(g2, wc.y, d);
            d = fmaf(g3, vf.z, d); d = fmaf(g4, vg.z, d);
            oo.y = __fdividef(a, d); }
        {   float a = p0.z;
            a = fmaf(g0, pa.z, a); a = fmaf(g1, pb.z, a); a = fmaf(g2, pc.z, a);
            a = fmaf(g3, qf.y, a); a = fmaf(g4, qg.y, a);
            float d = w0.z;
            d = fmaf(g0, wa.z, d); d = fmaf(g1, wb.z, d); d = fmaf(g2, wc.z, d);
            d = fmaf(g3, vf.y, d); d = fmaf(g4, vg.y, d);
            oo.z = __fdividef(a, d); }
        {   float a = p0.w;
            a = fmaf(g0, pa.w, a); a = fmaf(g1, pb.w, a); a = fmaf(g2, pc.w, a);
            a = fmaf(g3, qf.x, a); a = fmaf(g4, qg.x, a);
            float d = w0.w;
            d = fmaf(g0, wa.w, d); d = fmaf(g1, wb.w, d); d = fmaf(g2, wc.w, d);
            d = fmaf(g3, vf.x, d); d = fmaf(g4, vg.x, d);
            oo.w = __fdividef(a, d); }

        __stcs(&out4[base + o + 6 * m], oo);
    }
}

extern "C" void kernel_launch(void* const* d_in, const int* in_sizes, int n_in,
                              void* d_out, int out_size)
{
    const float4* x4 = (const float4*)d_in[0];
    const float*  s  = (const float*)d_in[1];
    const float4* w4 = (const float4*)d_in[2];
    float4* out4 = (float4*)d_out;

    const long long total = in_sizes[0];          // B*C*H*W = 14,155,776
    const int B = in_sizes[1] / 5;                // 16
    const long long rows = total / 96;            // 147,456
    const int rows_per_batch = (int)(rows / B);   // 9216

    const long long nthreads = rows * 6;          // 884,736 (2 per orbit-pair)
    const long long nblocks  = nthreads / NT;     // 6912 (exact)
    symmetry_control_bfly<<<(unsigned)nblocks, NT>>>(x4, s, w4, out4, rows_per_batch);
}